// round 14
// baseline (speedup 1.0000x reference)
#include <cuda_runtime.h>
#include <math.h>
#include <stdint.h>

#define Bb 16
#define II 512
#define HH 1024
#define BH (Bb*HH)            // 16384
#define NKC 6                 // K-chunks of 256 columns

// Output offsets (floats): h, c, e_w_ix, e_w_ih, e_b_i, e_w_fx, e_w_fh, e_b_f, e_w_cx, e_w_ch, e_b_c
#define OFF_H     0
#define OFF_C     16384
#define OFF_EWIX  32768
#define OFF_EWIH  8421376
#define OFF_EBI   25198592
#define OFF_EWFX  25214976
#define OFF_EWFH  33603584
#define OFF_EBF   50380800
#define OFF_EWCX  50397184
#define OFF_EWCH  58785792
#define OFF_EBC   75563008

// Scratch (no allocation allowed).
// Layout: g_part[kc][g][j*16 + b]
__device__ float g_part[NKC][4][HH * Bb];

struct GatePtrs {
    const float* wx[4];
    const float* wh[4];
};

__device__ __forceinline__ uint32_t to_tf32(float f) {
    uint32_t r;
    asm("cvt.rna.tf32.f32 %0, %1;" : "=r"(r) : "f"(f));
    return r;
}

__device__ __forceinline__ void mma_tf32(
    float d[4], uint32_t a0, uint32_t a1, uint32_t a2, uint32_t a3,
    uint32_t b0, uint32_t b1)
{
    asm volatile(
        "mma.sync.aligned.m16n8k8.row.col.f32.tf32.tf32.f32 "
        "{%0,%1,%2,%3}, {%4,%5,%6,%7}, {%8,%9}, {%0,%1,%2,%3};"
        : "+f"(d[0]), "+f"(d[1]), "+f"(d[2]), "+f"(d[3])
        : "r"(a0), "r"(a1), "r"(a2), "r"(a3), "r"(b0), "r"(b1));
}

// ---------------------------------------------------------------------------
// Kernel 1: gate pre-activation partials via tf32 mma.sync.
// grid = (HH/64, 4 gates, 6 K-chunks of 256), block = 128 (4 warps).
// Each warp: 16 j (two m16n8k8 n-tiles) x 16 batches x K=256 (32 k-steps).
// Fragments loaded directly from gmem at natural per-thread addresses:
//   A (z, row):  a0=(b=g,k=t4) a1=(b=g+8,k=t4) a2=(b=g,k=t4+4) a3=(b=g+8,k=t4+4)
//   B (W, col):  b0=W[j0+g][k0+t4], b1=W[j0+g][k0+t4+4]
//   D (f32):     d0=(b=g,j=2t4) d1=(g,2t4+1) d2=(g+8,2t4) d3=(g+8,2t4+1)
// Weights read exactly once (25 MB DRAM); z traffic shared across 16 j/warp.
// No cross-lane reduction — mma accumulates in fp32.
// ---------------------------------------------------------------------------
__global__ __launch_bounds__(128) void gates_kernel(
    const float* __restrict__ x, const float* __restrict__ h_last, GatePtrs p)
{
    const int tid  = threadIdx.x;
    const int warp = tid >> 5;
    const int lane = tid & 31;
    const int gq   = lane >> 2;    // 0..7
    const int t4   = lane & 3;     // 0..3

    const int kc  = blockIdx.z;
    const int g   = blockIdx.y;
    const int j0w = blockIdx.x * 64 + warp * 16;

    const float* wbase = (kc < 2) ? p.wx[g] : p.wh[g];
    const int rowlen   = (kc < 2) ? II : HH;
    const int k00      = (kc < 2) ? kc * 256 : (kc - 2) * 256;
    const float* zsrc  = (kc < 2) ? x : h_last;

    // Per-thread base pointers for fragment loads
    const float* zr0 = zsrc + gq * rowlen + k00 + t4;          // batch g
    const float* zr1 = zsrc + (gq + 8) * rowlen + k00 + t4;    // batch g+8
    const float* w0r = wbase + (size_t)(j0w + gq) * rowlen + k00 + t4;      // tile 0
    const float* w1r = wbase + (size_t)(j0w + 8 + gq) * rowlen + k00 + t4;  // tile 1

    float d0[4] = {0.f, 0.f, 0.f, 0.f};
    float d1[4] = {0.f, 0.f, 0.f, 0.f};

#pragma unroll 8
    for (int ks = 0; ks < 32; ks++) {
        const int kb = ks * 8;
        // A fragment (z)
        float a0f = __ldg(zr0 + kb);
        float a1f = __ldg(zr1 + kb);
        float a2f = __ldg(zr0 + kb + 4);
        float a3f = __ldg(zr1 + kb + 4);
        // B fragments (weights, read once)
        float b00f = __ldg(w0r + kb);
        float b01f = __ldg(w0r + kb + 4);
        float b10f = __ldg(w1r + kb);
        float b11f = __ldg(w1r + kb + 4);

        uint32_t a0 = to_tf32(a0f), a1 = to_tf32(a1f);
        uint32_t a2 = to_tf32(a2f), a3 = to_tf32(a3f);

        mma_tf32(d0, a0, a1, a2, a3, to_tf32(b00f), to_tf32(b01f));
        mma_tf32(d1, a0, a1, a2, a3, to_tf32(b10f), to_tf32(b11f));
    }

    // Scatter-store partials: g_part[kc][g][j*16 + b]
    float* dst = g_part[kc][g];
    const int jc0 = j0w + 2 * t4;        // tile 0 columns jc0, jc0+1
    const int jc1 = jc0 + 8;             // tile 1
    dst[(jc0    ) * Bb + gq    ] = d0[0];
    dst[(jc0 + 1) * Bb + gq    ] = d0[1];
    dst[(jc0    ) * Bb + gq + 8] = d0[2];
    dst[(jc0 + 1) * Bb + gq + 8] = d0[3];
    dst[(jc1    ) * Bb + gq    ] = d1[0];
    dst[(jc1 + 1) * Bb + gq    ] = d1[1];
    dst[(jc1    ) * Bb + gq + 8] = d1[2];
    dst[(jc1 + 1) * Bb + gq + 8] = d1[3];
}

// ---------------------------------------------------------------------------
// Kernel 2: fused pointwise + HBM-bound trace update (proven 5.9 TB/s).
// ---------------------------------------------------------------------------
#define JT 16

__global__ __launch_bounds__(256) void trace_kernel(
    const float* __restrict__ x, const float* __restrict__ h_last,
    const float* __restrict__ c_last,
    const float* __restrict__ b_i, const float* __restrict__ b_f,
    const float* __restrict__ b_o, const float* __restrict__ b_c,
    const float* __restrict__ eb_i, const float* __restrict__ eb_f,
    const float* __restrict__ eb_c,
    const float* __restrict__ e_ix, const float* __restrict__ e_ih,
    const float* __restrict__ e_fx, const float* __restrict__ e_fh,
    const float* __restrict__ e_cx, const float* __restrict__ e_ch,
    float* __restrict__ out)
{
    __shared__ float4 sx[II / 4];   // 2KB
    __shared__ float4 sh[HH / 4];   // 4KB
    __shared__ float4 scf[JT];

    const int tid = threadIdx.x;
    const int b   = blockIdx.y;
    const int j0  = blockIdx.x * JT;

    if (tid < 128) sx[tid] = ((const float4*)(x + b * II))[tid];
    sh[tid] = ((const float4*)(h_last + b * HH))[tid];

    if (tid < JT) {
        const int j   = j0 + tid;
        const int idx = b * HH + j;
        const int gi  = j * Bb + b;

        float pi = b_i[j], pf = b_f[j], po = b_o[j], pc = b_c[j];
#pragma unroll
        for (int c = 0; c < NKC; c++) {
            pi += g_part[c][0][gi];
            pf += g_part[c][1][gi];
            po += g_part[c][2][gi];
            pc += g_part[c][3][gi];
        }

        float i  = 1.f / (1.f + expf(-pi));
        float f  = 1.f / (1.f + expf(-pf));
        float o  = 1.f / (1.f + expf(-po));
        float ch = tanhf(pc);
        float cl = c_last[idx];

        float c = fmaf(f, cl, i * ch);
        float h = o * c;
        float di  = i * (1.f - i);
        float df  = f * (1.f - f);
        float dch = 1.f - ch * ch;
        float ai = di * ch;
        float af = df * cl;
        float ac = dch * i;

        out[OFF_H + idx]   = h;
        out[OFF_C + idx]   = c;
        out[OFF_EBI + idx] = fmaf(eb_i[idx], f, ai);
        out[OFF_EBF + idx] = fmaf(eb_f[idx], f, af);
        out[OFF_EBC + idx] = fmaf(eb_c[idx], f, ac);
        scf[tid] = make_float4(f, ai, af, ac);
    }
    __syncthreads();

    const size_t baseH = (size_t)(b * HH + j0) * (HH / 4);
    const size_t baseI = (size_t)(b * HH + j0) * (II / 4);

    const float4 hv = sh[tid];
    const float4 xv = sx[tid & 127];
    const int xsel = tid >> 7;

#define TRACE_H(SRC, OFF, SEL)                                              \
    {                                                                       \
        const float4* ein = (const float4*)(SRC) + baseH;                   \
        float4* eo = (float4*)(out + (OFF)) + baseH;                        \
        _Pragma("unroll")                                                   \
        for (int it = 0; it < JT; it++) {                                   \
            const int t = tid + it * 256;                                   \
            float4 cf = scf[it];                                            \
            float fv = cf.x, aa = cf.SEL;                                   \
            float4 e  = __ldcs(ein + t);                                    \
            float4 rr;                                                      \
            rr.x = fmaf(e.x, fv, aa * hv.x);                                \
            rr.y = fmaf(e.y, fv, aa * hv.y);                                \
            rr.z = fmaf(e.z, fv, aa * hv.z);                                \
            rr.w = fmaf(e.w, fv, aa * hv.w);                                \
            __stcs(eo + t, rr);                                             \
        }                                                                   \
    }

#define TRACE_X(SRC, OFF, SEL)                                              \
    {                                                                       \
        const float4* ein = (const float4*)(SRC) + baseI;                   \
        float4* eo = (float4*)(out + (OFF)) + baseI;                        \
        _Pragma("unroll")                                                   \
        for (int it = 0; it < JT / 2; it++) {                               \
            const int t = tid + it * 256;                                   \
            float4 cf = scf[it * 2 + xsel];                                 \
            float fv = cf.x, aa = cf.SEL;                                   \
            float4 e  = __ldcs(ein + t);                                    \
            float4 rr;                                                      \
            rr.x = fmaf(e.x, fv, aa * xv.x);                                \
            rr.y = fmaf(e.y, fv, aa * xv.y);                                \
            rr.z = fmaf(e.z, fv, aa * xv.z);                                \
            rr.w = fmaf(e.w, fv, aa * xv.w);                                \
            __stcs(eo + t, rr);                                             \
        }                                                                   \
    }

    TRACE_H(e_ih, OFF_EWIH, y)
    TRACE_H(e_fh, OFF_EWFH, z)
    TRACE_H(e_ch, OFF_EWCH, w)
    TRACE_X(e_ix, OFF_EWIX, y)
    TRACE_X(e_fx, OFF_EWFX, z)
    TRACE_X(e_cx, OFF_EWCX, w)
}

// ---------------------------------------------------------------------------
extern "C" void kernel_launch(void* const* d_in, const int* in_sizes, int n_in,
                              void* d_out, int out_size)
{
    const float* x      = (const float*)d_in[0];
    const float* w_ix   = (const float*)d_in[1];
    const float* w_ih   = (const float*)d_in[2];
    const float* b_i    = (const float*)d_in[3];
    const float* w_fx   = (const float*)d_in[4];
    const float* w_fh   = (const float*)d_in[5];
    const float* b_f    = (const float*)d_in[6];
    const float* w_ox   = (const float*)d_in[7];
    const float* w_oh   = (const float*)d_in[8];
    const float* b_o    = (const float*)d_in[9];
    const float* w_cx   = (const float*)d_in[10];
    const float* w_ch   = (const float*)d_in[11];
    const float* b_c    = (const float*)d_in[12];
    const float* h_last = (const float*)d_in[13];
    const float* c_last = (const float*)d_in[14];
    const float* e_w_ix = (const float*)d_in[15];
    const float* e_w_ih = (const float*)d_in[16];
    const float* e_b_i  = (const float*)d_in[17];
    const float* e_w_fx = (const float*)d_in[18];
    const float* e_w_fh = (const float*)d_in[19];
    const float* e_b_f  = (const float*)d_in[20];
    const float* e_w_cx = (const float*)d_in[21];
    const float* e_w_ch = (const float*)d_in[22];
    const float* e_b_c  = (const float*)d_in[23];
    float* out = (float*)d_out;

    GatePtrs p;
    p.wx[0] = w_ix; p.wx[1] = w_fx; p.wx[2] = w_ox; p.wx[3] = w_cx;
    p.wh[0] = w_ih; p.wh[1] = w_fh; p.wh[2] = w_oh; p.wh[3] = w_ch;

    dim3 g1(HH / 64, 4, NKC);   // 16 x 4 x 6 = 384 blocks
    gates_kernel<<<g1, 128>>>(x, h_last, p);

    dim3 g3(HH / JT, Bb);
    trace_kernel<<<g3, 256>>>(x, h_last, c_last, b_i, b_f, b_o, b_c,
                              e_b_i, e_b_f, e_b_c,
                              e_w_ix, e_w_ih, e_w_fx, e_w_fh,
                              e_w_cx, e_w_ch, out);
}

// round 15
// speedup vs baseline: 1.0132x; 1.0132x over previous
#include <cuda_runtime.h>
#include <math.h>
#include <stdint.h>

#define Bb 16
#define II 512
#define HH 1024
#define BH (Bb*HH)            // 16384
#define NKC 12                // K-chunks of 128 columns (4 from x, 8 from h)

// Output offsets (floats): h, c, e_w_ix, e_w_ih, e_b_i, e_w_fx, e_w_fh, e_b_f, e_w_cx, e_w_ch, e_b_c
#define OFF_H     0
#define OFF_C     16384
#define OFF_EWIX  32768
#define OFF_EWIH  8421376
#define OFF_EBI   25198592
#define OFF_EWFX  25214976
#define OFF_EWFH  33603584
#define OFF_EBF   50380800
#define OFF_EWCX  50397184
#define OFF_EWCH  58785792
#define OFF_EBC   75563008

// Scratch (no allocation allowed). Layout: g_part[kc][g][j*16 + b]
__device__ float g_part[NKC][4][HH * Bb];

struct GatePtrs {
    const float* wx[4];
    const float* wh[4];
};

__device__ __forceinline__ uint32_t to_tf32(float f) {
    uint32_t r;
    asm("cvt.rna.tf32.f32 %0, %1;" : "=r"(r) : "f"(f));
    return r;
}

__device__ __forceinline__ void mma_tf32(
    float d[4], uint32_t a0, uint32_t a1, uint32_t a2, uint32_t a3,
    uint32_t b0, uint32_t b1)
{
    asm volatile(
        "mma.sync.aligned.m16n8k8.row.col.f32.tf32.tf32.f32 "
        "{%0,%1,%2,%3}, {%4,%5,%6,%7}, {%8,%9}, {%0,%1,%2,%3};"
        : "+f"(d[0]), "+f"(d[1]), "+f"(d[2]), "+f"(d[3])
        : "r"(a0), "r"(a1), "r"(a2), "r"(a3), "r"(b0), "r"(b1));
}

// ---------------------------------------------------------------------------
// Kernel 1: gate pre-activations via tf32 mma, weights staged through smem.
// grid = (HH/64, 4 gates, 12 K-chunks of 128), block = 128 (4 warps).
// Each warp: 16 j (two m16n8k8 n-tiles) x 16 batches x K=128.
// Weight tile (16j x 32k) loaded as coalesced float4 (one 128B row segment
// per 8 lanes), stored to pad-36 smem (bank = 4*gq+t4 -> conflict-free LDS).
// z (a-frag) loaded directly from the L1-resident 96KB x/h working set.
// mma fragment mapping identical to R14 (validated, rel_err 3.5e-4).
// ---------------------------------------------------------------------------
__global__ __launch_bounds__(128) void gates_kernel(
    const float* __restrict__ x, const float* __restrict__ h_last, GatePtrs p)
{
    __shared__ float wbuf[4][16][36];   // [warp][row][32k + pad4], 9216B

    const int tid  = threadIdx.x;
    const int warp = tid >> 5;
    const int lane = tid & 31;
    const int gq   = lane >> 2;    // 0..7
    const int t4   = lane & 3;     // 0..3

    const int kc  = blockIdx.z;
    const int g   = blockIdx.y;
    const int j0w = blockIdx.x * 64 + warp * 16;

    const float* wbase = (kc < 4) ? p.wx[g] : p.wh[g];
    const int rowlen   = (kc < 4) ? II : HH;
    const int k00      = (kc < 4) ? kc * 128 : (kc - 4) * 128;
    const float* zsrc  = (kc < 4) ? x : h_last;

    const float* zr0 = zsrc + gq * rowlen + k00 + t4;          // batch gq
    const float* zr1 = zsrc + (gq + 8) * rowlen + k00 + t4;    // batch gq+8

    float d0[4] = {0.f, 0.f, 0.f, 0.f};
    float d1[4] = {0.f, 0.f, 0.f, 0.f};

    float (*wb)[36] = wbuf[warp];

#pragma unroll
    for (int mc = 0; mc < 4; mc++) {          // k32 macro steps
        const int kbase = k00 + mc * 32;

        // Stage W tile: 16 rows x 8 float4, coalesced
#pragma unroll
        for (int it = 0; it < 4; it++) {
            const int idx = it * 32 + lane;
            const int row = idx >> 3;
            const int kq  = idx & 7;
            float4 v = __ldg((const float4*)(wbase + (size_t)(j0w + row) * rowlen + kbase) + kq);
            *(float4*)&wb[row][kq * 4] = v;
        }
        __syncwarp();

#pragma unroll
        for (int ks = 0; ks < 4; ks++) {
            const int kb = mc * 32 + ks * 8;   // z offset within chunk
            // A fragment (z) — direct, L1-resident
            float a0f = __ldg(zr0 + kb);
            float a1f = __ldg(zr1 + kb);
            float a2f = __ldg(zr0 + kb + 4);
            float a3f = __ldg(zr1 + kb + 4);
            // B fragments (W) — conflict-free LDS
            float b00f = wb[gq][ks * 8 + t4];
            float b01f = wb[gq][ks * 8 + t4 + 4];
            float b10f = wb[8 + gq][ks * 8 + t4];
            float b11f = wb[8 + gq][ks * 8 + t4 + 4];

            uint32_t a0 = to_tf32(a0f), a1 = to_tf32(a1f);
            uint32_t a2 = to_tf32(a2f), a3 = to_tf32(a3f);

            mma_tf32(d0, a0, a1, a2, a3, to_tf32(b00f), to_tf32(b01f));
            mma_tf32(d1, a0, a1, a2, a3, to_tf32(b10f), to_tf32(b11f));
        }
        __syncwarp();
    }

    // Scatter-store partials (identical to validated R14 mapping)
    float* dst = g_part[kc][g];
    const int jc0 = j0w + 2 * t4;
    const int jc1 = jc0 + 8;
    dst[(jc0    ) * Bb + gq    ] = d0[0];
    dst[(jc0 + 1) * Bb + gq    ] = d0[1];
    dst[(jc0    ) * Bb + gq + 8] = d0[2];
    dst[(jc0 + 1) * Bb + gq + 8] = d0[3];
    dst[(jc1    ) * Bb + gq    ] = d1[0];
    dst[(jc1 + 1) * Bb + gq    ] = d1[1];
    dst[(jc1    ) * Bb + gq + 8] = d1[2];
    dst[(jc1 + 1) * Bb + gq + 8] = d1[3];
}

// ---------------------------------------------------------------------------
// Kernel 2: fused pointwise + HBM-bound trace update (proven 5.9 TB/s).
// ---------------------------------------------------------------------------
#define JT 16

__global__ __launch_bounds__(256) void trace_kernel(
    const float* __restrict__ x, const float* __restrict__ h_last,
    const float* __restrict__ c_last,
    const float* __restrict__ b_i, const float* __restrict__ b_f,
    const float* __restrict__ b_o, const float* __restrict__ b_c,
    const float* __restrict__ eb_i, const float* __restrict__ eb_f,
    const float* __restrict__ eb_c,
    const float* __restrict__ e_ix, const float* __restrict__ e_ih,
    const float* __restrict__ e_fx, const float* __restrict__ e_fh,
    const float* __restrict__ e_cx, const float* __restrict__ e_ch,
    float* __restrict__ out)
{
    __shared__ float4 sx[II / 4];   // 2KB
    __shared__ float4 sh[HH / 4];   // 4KB
    __shared__ float4 scf[JT];

    const int tid = threadIdx.x;
    const int b   = blockIdx.y;
    const int j0  = blockIdx.x * JT;

    if (tid < 128) sx[tid] = ((const float4*)(x + b * II))[tid];
    sh[tid] = ((const float4*)(h_last + b * HH))[tid];

    if (tid < JT) {
        const int j   = j0 + tid;
        const int idx = b * HH + j;
        const int gi  = j * Bb + b;

        float pi = b_i[j], pf = b_f[j], po = b_o[j], pc = b_c[j];
#pragma unroll
        for (int c = 0; c < NKC; c++) {
            pi += g_part[c][0][gi];
            pf += g_part[c][1][gi];
            po += g_part[c][2][gi];
            pc += g_part[c][3][gi];
        }

        float i  = 1.f / (1.f + expf(-pi));
        float f  = 1.f / (1.f + expf(-pf));
        float o  = 1.f / (1.f + expf(-po));
        float ch = tanhf(pc);
        float cl = c_last[idx];

        float c = fmaf(f, cl, i * ch);
        float h = o * c;
        float di  = i * (1.f - i);
        float df  = f * (1.f - f);
        float dch = 1.f - ch * ch;
        float ai = di * ch;
        float af = df * cl;
        float ac = dch * i;

        out[OFF_H + idx]   = h;
        out[OFF_C + idx]   = c;
        out[OFF_EBI + idx] = fmaf(eb_i[idx], f, ai);
        out[OFF_EBF + idx] = fmaf(eb_f[idx], f, af);
        out[OFF_EBC + idx] = fmaf(eb_c[idx], f, ac);
        scf[tid] = make_float4(f, ai, af, ac);
    }
    __syncthreads();

    const size_t baseH = (size_t)(b * HH + j0) * (HH / 4);
    const size_t baseI = (size_t)(b * HH + j0) * (II / 4);

    const float4 hv = sh[tid];
    const float4 xv = sx[tid & 127];
    const int xsel = tid >> 7;

#define TRACE_H(SRC, OFF, SEL)                                              \
    {                                                                       \
        const float4* ein = (const float4*)(SRC) + baseH;                   \
        float4* eo = (float4*)(out + (OFF)) + baseH;                        \
        _Pragma("unroll")                                                   \
        for (int it = 0; it < JT; it++) {                                   \
            const int t = tid + it * 256;                                   \
            float4 cf = scf[it];                                            \
            float fv = cf.x, aa = cf.SEL;                                   \
            float4 e  = __ldcs(ein + t);                                    \
            float4 rr;                                                      \
            rr.x = fmaf(e.x, fv, aa * hv.x);                                \
            rr.y = fmaf(e.y, fv, aa * hv.y);                                \
            rr.z = fmaf(e.z, fv, aa * hv.z);                                \
            rr.w = fmaf(e.w, fv, aa * hv.w);                                \
            __stcs(eo + t, rr);                                             \
        }                                                                   \
    }

#define TRACE_X(SRC, OFF, SEL)                                              \
    {                                                                       \
        const float4* ein = (const float4*)(SRC) + baseI;                   \
        float4* eo = (float4*)(out + (OFF)) + baseI;                        \
        _Pragma("unroll")                                                   \
        for (int it = 0; it < JT / 2; it++) {                               \
            const int t = tid + it * 256;                                   \
            float4 cf = scf[it * 2 + xsel];                                 \
            float fv = cf.x, aa = cf.SEL;                                   \
            float4 e  = __ldcs(ein + t);                                    \
            float4 rr;                                                      \
            rr.x = fmaf(e.x, fv, aa * xv.x);                                \
            rr.y = fmaf(e.y, fv, aa * xv.y);                                \
            rr.z = fmaf(e.z, fv, aa * xv.z);                                \
            rr.w = fmaf(e.w, fv, aa * xv.w);                                \
            __stcs(eo + t, rr);                                             \
        }                                                                   \
    }

    TRACE_H(e_ih, OFF_EWIH, y)
    TRACE_H(e_fh, OFF_EWFH, z)
    TRACE_H(e_ch, OFF_EWCH, w)
    TRACE_X(e_ix, OFF_EWIX, y)
    TRACE_X(e_fx, OFF_EWFX, z)
    TRACE_X(e_cx, OFF_EWCX, w)
}

// ---------------------------------------------------------------------------
extern "C" void kernel_launch(void* const* d_in, const int* in_sizes, int n_in,
                              void* d_out, int out_size)
{
    const float* x      = (const float*)d_in[0];
    const float* w_ix   = (const float*)d_in[1];
    const float* w_ih   = (const float*)d_in[2];
    const float* b_i    = (const float*)d_in[3];
    const float* w_fx   = (const float*)d_in[4];
    const float* w_fh   = (const float*)d_in[5];
    const float* b_f    = (const float*)d_in[6];
    const float* w_ox   = (const float*)d_in[7];
    const float* w_oh   = (const float*)d_in[8];
    const float* b_o    = (const float*)d_in[9];
    const float* w_cx   = (const float*)d_in[10];
    const float* w_ch   = (const float*)d_in[11];
    const float* b_c    = (const float*)d_in[12];
    const float* h_last = (const float*)d_in[13];
    const float* c_last = (const float*)d_in[14];
    const float* e_w_ix = (const float*)d_in[15];
    const float* e_w_ih = (const float*)d_in[16];
    const float* e_b_i  = (const float*)d_in[17];
    const float* e_w_fx = (const float*)d_in[18];
    const float* e_w_fh = (const float*)d_in[19];
    const float* e_b_f  = (const float*)d_in[20];
    const float* e_w_cx = (const float*)d_in[21];
    const float* e_w_ch = (const float*)d_in[22];
    const float* e_b_c  = (const float*)d_in[23];
    float* out = (float*)d_out;

    GatePtrs p;
    p.wx[0] = w_ix; p.wx[1] = w_fx; p.wx[2] = w_ox; p.wx[3] = w_cx;
    p.wh[0] = w_ih; p.wh[1] = w_fh; p.wh[2] = w_oh; p.wh[3] = w_ch;

    dim3 g1(HH / 64, 4, NKC);   // 16 x 4 x 12 = 768 blocks
    gates_kernel<<<g1, 128>>>(x, h_last, p);

    dim3 g3(HH / JT, Bb);
    trace_kernel<<<g3, 256>>>(x, h_last, c_last, b_i, b_f, b_o, b_c,
                              e_b_i, e_b_f, e_b_c,
                              e_w_ix, e_w_ih, e_w_fx, e_w_fh,
                              e_w_cx, e_w_ch, out);
}

// round 16
// speedup vs baseline: 1.0321x; 1.0186x over previous
#include <cuda_runtime.h>
#include <math.h>

#define Bb 16
#define II 512
#define HH 1024
#define BH (Bb*HH)            // 16384
#define NKC 6                 // K-chunks of 256 columns

// Output offsets (floats): h, c, e_w_ix, e_w_ih, e_b_i, e_w_fx, e_w_fh, e_b_f, e_w_cx, e_w_ch, e_b_c
#define OFF_H     0
#define OFF_C     16384
#define OFF_EWIX  32768
#define OFF_EWIH  8421376
#define OFF_EBI   25198592
#define OFF_EWFX  25214976
#define OFF_EWFH  33603584
#define OFF_EBF   50380800
#define OFF_EWCX  50397184
#define OFF_EWCH  58785792
#define OFF_EBC   75563008

// Scratch (no allocation allowed)
__device__ float g_part[NKC][4 * BH];   // partial pre-activations per K-chunk

struct GatePtrs {
    const float* wx[4];
    const float* wh[4];
};

typedef unsigned long long u64;

__device__ __forceinline__ u64 pack2(float lo, float hi) {
    u64 r;
    asm("mov.b64 %0, {%1, %2};" : "=l"(r) : "f"(lo), "f"(hi));
    return r;
}
__device__ __forceinline__ void fma2(u64& acc, u64 a, u64 b) {
    asm("fma.rn.f32x2 %0, %1, %2, %0;" : "+l"(acc) : "l"(a), "l"(b));
}
__device__ __forceinline__ void unpack2(u64 v, float& lo, float& hi) {
    asm("mov.b64 {%0, %1}, %2;" : "=f"(lo), "=f"(hi) : "l"(v));
}

// ---------------------------------------------------------------------------
// Kernel 1: gate pre-activation partials with packed f32x2 FMA (R11, best).
// grid = (HH/16, 4 gates, 6 K-chunks of 256 cols), block = 128 (4 warps).
// ---------------------------------------------------------------------------
__global__ __launch_bounds__(128, 4) void gates_kernel(
    const float* __restrict__ x, const float* __restrict__ h_last, GatePtrs p)
{
    const int tid  = threadIdx.x;
    const int warp = tid >> 5;
    const int lane = tid & 31;
    const int kc   = blockIdx.z;
    const int g    = blockIdx.y;
    const int j0   = blockIdx.x * 16 + warp * 4;

    const float* wbase = (kc < 2) ? p.wx[g] : p.wh[g];
    const int rowlen   = (kc < 2) ? II : HH;
    const int koff     = (kc < 2) ? kc * 256 : (kc - 2) * 256;

    const float4* zsrc = (kc < 2) ? (const float4*)x : (const float4*)h_last;
    const int rowf4    = (kc < 2) ? (II / 4) : (HH / 4);
    const int zoff     = (kc < 2) ? kc * 64 : (kc - 2) * 64;

    u64 acc[32];
#pragma unroll
    for (int m = 0; m < 32; m++) acc[m] = 0ull;

#pragma unroll
    for (int it = 0; it < 2; it++) {
        float4 wr[4];
#pragma unroll
        for (int r = 0; r < 4; r++)
            wr[r] = *((const float4*)(wbase + (size_t)(j0 + r) * rowlen + koff)
                      + it * 32 + lane);

        u64 w2[4][4];
#pragma unroll
        for (int r = 0; r < 4; r++) {
            w2[r][0] = pack2(wr[r].x, wr[r].x);
            w2[r][1] = pack2(wr[r].y, wr[r].y);
            w2[r][2] = pack2(wr[r].z, wr[r].z);
            w2[r][3] = pack2(wr[r].w, wr[r].w);
        }

        const int k4 = zoff + it * 32 + lane;
#pragma unroll
        for (int bp = 0; bp < 8; bp++) {
            float4 zl = __ldg(zsrc + (2 * bp)     * rowf4 + k4);
            float4 zh = __ldg(zsrc + (2 * bp + 1) * rowf4 + k4);
            u64 z0 = pack2(zl.x, zh.x);
            u64 z1 = pack2(zl.y, zh.y);
            u64 z2 = pack2(zl.z, zh.z);
            u64 z3 = pack2(zl.w, zh.w);
#pragma unroll
            for (int r = 0; r < 4; r++) {
                fma2(acc[r * 8 + bp], w2[r][0], z0);
                fma2(acc[r * 8 + bp], w2[r][1], z1);
                fma2(acc[r * 8 + bp], w2[r][2], z2);
                fma2(acc[r * 8 + bp], w2[r][3], z3);
            }
        }
    }

    float a[64];
#pragma unroll
    for (int r = 0; r < 4; r++)
#pragma unroll
        for (int bp = 0; bp < 8; bp++)
            unpack2(acc[r * 8 + bp], a[r * 16 + 2 * bp], a[r * 16 + 2 * bp + 1]);

    // Multi-value butterfly reduction: 64 values -> 2 per lane (62 shuffles).
#pragma unroll
    for (int k = 0; k < 5; k++) {
        const int d = 1 << k;
        const int n = 64 >> k;
        const bool hi = (lane >> k) & 1;
#pragma unroll
        for (int m = 0; m < 32; m++) {
            if (m < n / 2) {
                float mine = hi ? a[m] : a[m + n / 2];
                float got  = __shfl_xor_sync(0xffffffffu, mine, d);
                a[m] = (hi ? a[m + n / 2] : a[m]) + got;
            }
        }
    }

    const unsigned rev = __brev((unsigned)lane) >> 27;
#pragma unroll
    for (int j = 0; j < 2; j++) {
        const unsigned v = (rev << 1) | j;
        const int jj = v >> 4;
        const int b  = v & 15;
        g_part[kc][g * BH + b * HH + j0 + jj] = a[j];
    }
}

// ---------------------------------------------------------------------------
// Kernel 2: fused pointwise + HBM-bound trace update, launched with PDL.
// Blocks start during gates' drain, stage sx/sh (gates-independent), then
// cudaGridDependencySynchronize() before consuming g_part.
// ---------------------------------------------------------------------------
#define JT 16

__global__ __launch_bounds__(256) void trace_kernel(
    const float* __restrict__ x, const float* __restrict__ h_last,
    const float* __restrict__ c_last,
    const float* __restrict__ b_i, const float* __restrict__ b_f,
    const float* __restrict__ b_o, const float* __restrict__ b_c,
    const float* __restrict__ eb_i, const float* __restrict__ eb_f,
    const float* __restrict__ eb_c,
    const float* __restrict__ e_ix, const float* __restrict__ e_ih,
    const float* __restrict__ e_fx, const float* __restrict__ e_fh,
    const float* __restrict__ e_cx, const float* __restrict__ e_ch,
    float* __restrict__ out)
{
    __shared__ float4 sx[II / 4];   // 2KB
    __shared__ float4 sh[HH / 4];   // 4KB
    __shared__ float4 scf[JT];

    const int tid = threadIdx.x;
    const int b   = blockIdx.y;
    const int j0  = blockIdx.x * JT;

    // Gates-independent prologue (overlaps the gates kernel under PDL)
    if (tid < 128) sx[tid] = ((const float4*)(x + b * II))[tid];
    sh[tid] = ((const float4*)(h_last + b * HH))[tid];

    // Wait for gates_kernel's g_part writes to be visible.
    cudaGridDependencySynchronize();

    if (tid < JT) {
        const int j   = j0 + tid;
        const int idx = b * HH + j;

        float pi = b_i[j], pf = b_f[j], po = b_o[j], pc = b_c[j];
#pragma unroll
        for (int c = 0; c < NKC; c++) {
            pi += g_part[c][0 * BH + idx];
            pf += g_part[c][1 * BH + idx];
            po += g_part[c][2 * BH + idx];
            pc += g_part[c][3 * BH + idx];
        }

        float i  = 1.f / (1.f + expf(-pi));
        float f  = 1.f / (1.f + expf(-pf));
        float o  = 1.f / (1.f + expf(-po));
        float ch = tanhf(pc);
        float cl = c_last[idx];

        float c = fmaf(f, cl, i * ch);
        float h = o * c;
        float di  = i * (1.f - i);
        float df  = f * (1.f - f);
        float dch = 1.f - ch * ch;
        float ai = di * ch;
        float af = df * cl;
        float ac = dch * i;

        out[OFF_H + idx]   = h;
        out[OFF_C + idx]   = c;
        out[OFF_EBI + idx] = fmaf(eb_i[idx], f, ai);
        out[OFF_EBF + idx] = fmaf(eb_f[idx], f, af);
        out[OFF_EBC + idx] = fmaf(eb_c[idx], f, ac);
        scf[tid] = make_float4(f, ai, af, ac);
    }
    __syncthreads();

    const size_t baseH = (size_t)(b * HH + j0) * (HH / 4);
    const size_t baseI = (size_t)(b * HH + j0) * (II / 4);

    const float4 hv = sh[tid];
    const float4 xv = sx[tid & 127];
    const int xsel = tid >> 7;

#define TRACE_H(SRC, OFF, SEL)                                              \
    {                                                                       \
        const float4* ein = (const float4*)(SRC) + baseH;                   \
        float4* eo = (float4*)(out + (OFF)) + baseH;                        \
        _Pragma("unroll")                                                   \
        for (int it = 0; it < JT; it++) {                                   \
            const int t = tid + it * 256;                                   \
            float4 cf = scf[it];                                            \
            float fv = cf.x, aa = cf.SEL;                                   \
            float4 e  = __ldcs(ein + t);                                    \
            float4 rr;                                                      \
            rr.x = fmaf(e.x, fv, aa * hv.x);                                \
            rr.y = fmaf(e.y, fv, aa * hv.y);                                \
            rr.z = fmaf(e.z, fv, aa * hv.z);                                \
            rr.w = fmaf(e.w, fv, aa * hv.w);                                \
            __stcs(eo + t, rr);                                             \
        }                                                                   \
    }

#define TRACE_X(SRC, OFF, SEL)                                              \
    {                                                                       \
        const float4* ein = (const float4*)(SRC) + baseI;                   \
        float4* eo = (float4*)(out + (OFF)) + baseI;                        \
        _Pragma("unroll")                                                   \
        for (int it = 0; it < JT / 2; it++) {                               \
            const int t = tid + it * 256;                                   \
            float4 cf = scf[it * 2 + xsel];                                 \
            float fv = cf.x, aa = cf.SEL;                                   \
            float4 e  = __ldcs(ein + t);                                    \
            float4 rr;                                                      \
            rr.x = fmaf(e.x, fv, aa * xv.x);                                \
            rr.y = fmaf(e.y, fv, aa * xv.y);                                \
            rr.z = fmaf(e.z, fv, aa * xv.z);                                \
            rr.w = fmaf(e.w, fv, aa * xv.w);                                \
            __stcs(eo + t, rr);                                             \
        }                                                                   \
    }

    TRACE_H(e_ih, OFF_EWIH, y)
    TRACE_H(e_fh, OFF_EWFH, z)
    TRACE_H(e_ch, OFF_EWCH, w)
    TRACE_X(e_ix, OFF_EWIX, y)
    TRACE_X(e_fx, OFF_EWFX, z)
    TRACE_X(e_cx, OFF_EWCX, w)
}

// ---------------------------------------------------------------------------
extern "C" void kernel_launch(void* const* d_in, const int* in_sizes, int n_in,
                              void* d_out, int out_size)
{
    const float* x      = (const float*)d_in[0];
    const float* w_ix   = (const float*)d_in[1];
    const float* w_ih   = (const float*)d_in[2];
    const float* b_i    = (const float*)d_in[3];
    const float* w_fx   = (const float*)d_in[4];
    const float* w_fh   = (const float*)d_in[5];
    const float* b_f    = (const float*)d_in[6];
    const float* w_ox   = (const float*)d_in[7];
    const float* w_oh   = (const float*)d_in[8];
    const float* b_o    = (const float*)d_in[9];
    const float* w_cx   = (const float*)d_in[10];
    const float* w_ch   = (const float*)d_in[11];
    const float* b_c    = (const float*)d_in[12];
    const float* h_last = (const float*)d_in[13];
    const float* c_last = (const float*)d_in[14];
    const float* e_w_ix = (const float*)d_in[15];
    const float* e_w_ih = (const float*)d_in[16];
    const float* e_b_i  = (const float*)d_in[17];
    const float* e_w_fx = (const float*)d_in[18];
    const float* e_w_fh = (const float*)d_in[19];
    const float* e_b_f  = (const float*)d_in[20];
    const float* e_w_cx = (const float*)d_in[21];
    const float* e_w_ch = (const float*)d_in[22];
    const float* e_b_c  = (const float*)d_in[23];
    float* out = (float*)d_out;

    GatePtrs p;
    p.wx[0] = w_ix; p.wx[1] = w_fx; p.wx[2] = w_ox; p.wx[3] = w_cx;
    p.wh[0] = w_ih; p.wh[1] = w_fh; p.wh[2] = w_oh; p.wh[3] = w_ch;

    dim3 g1(HH / 16, 4, NKC);
    gates_kernel<<<g1, 128>>>(x, h_last, p);

    // Trace with Programmatic Dependent Launch: blocks may start during
    // gates' drain; they stage sx/sh, then gridDependencySynchronize()
    // before touching g_part.
    dim3 g3(HH / JT, Bb);
    cudaLaunchConfig_t cfg = {};
    cfg.gridDim = g3;
    cfg.blockDim = dim3(256, 1, 1);
    cfg.dynamicSmemBytes = 0;
    cfg.stream = 0;
    cudaLaunchAttribute attrs[1];
    attrs[0].id = cudaLaunchAttributeProgrammaticStreamSerialization;
    attrs[0].val.programmaticStreamSerializationAllowed = 1;
    cfg.attrs = attrs;
    cfg.numAttrs = 1;

    cudaLaunchKernelEx(&cfg, trace_kernel,
                       x, h_last, c_last, b_i, b_f, b_o, b_c,
                       e_b_i, e_b_f, e_b_c,
                       e_w_ix, e_w_ih, e_w_fx, e_w_fh,
                       e_w_cx, e_w_ch, out);
}

// round 17
// speedup vs baseline: 1.0339x; 1.0017x over previous
#include <cuda_runtime.h>
#include <math.h>

#define Bb 16
#define II 512
#define HH 1024
#define BH (Bb*HH)            // 16384
#define NKC 6                 // K-chunks of 256 columns

// Output offsets (floats): h, c, e_w_ix, e_w_ih, e_b_i, e_w_fx, e_w_fh, e_b_f, e_w_cx, e_w_ch, e_b_c
#define OFF_H     0
#define OFF_C     16384
#define OFF_EWIX  32768
#define OFF_EWIH  8421376
#define OFF_EBI   25198592
#define OFF_EWFX  25214976
#define OFF_EWFH  33603584
#define OFF_EBF   50380800
#define OFF_EWCX  50397184
#define OFF_EWCH  58785792
#define OFF_EBC   75563008

// Scratch (no allocation allowed)
__device__ float g_part[NKC][4 * BH];   // partial pre-activations per K-chunk

struct GatePtrs {
    const float* wx[4];
    const float* wh[4];
};

typedef unsigned long long u64;

__device__ __forceinline__ u64 pack2(float lo, float hi) {
    u64 r;
    asm("mov.b64 %0, {%1, %2};" : "=l"(r) : "f"(lo), "f"(hi));
    return r;
}
__device__ __forceinline__ void fma2(u64& acc, u64 a, u64 b) {
    asm("fma.rn.f32x2 %0, %1, %2, %0;" : "+l"(acc) : "l"(a), "l"(b));
}
__device__ __forceinline__ void unpack2(u64 v, float& lo, float& hi) {
    asm("mov.b64 {%0, %1}, %2;" : "=f"(lo), "=f"(hi) : "l"(v));
}

// ---------------------------------------------------------------------------
// Kernel 1: gate pre-activation partials with packed f32x2 FMA (R11, best).
// Triggers programmatic launch completion at ENTRY so the PDL-chained trace
// kernel launches immediately and overlaps its prologue with our compute.
// grid = (HH/16, 4 gates, 6 K-chunks of 256 cols), block = 128 (4 warps).
// ---------------------------------------------------------------------------
__global__ __launch_bounds__(128, 4) void gates_kernel(
    const float* __restrict__ x, const float* __restrict__ h_last, GatePtrs p)
{
    cudaTriggerProgrammaticLaunchCompletion();

    const int tid  = threadIdx.x;
    const int warp = tid >> 5;
    const int lane = tid & 31;
    const int kc   = blockIdx.z;
    const int g    = blockIdx.y;
    const int j0   = blockIdx.x * 16 + warp * 4;

    const float* wbase = (kc < 2) ? p.wx[g] : p.wh[g];
    const int rowlen   = (kc < 2) ? II : HH;
    const int koff     = (kc < 2) ? kc * 256 : (kc - 2) * 256;

    const float4* zsrc = (kc < 2) ? (const float4*)x : (const float4*)h_last;
    const int rowf4    = (kc < 2) ? (II / 4) : (HH / 4);
    const int zoff     = (kc < 2) ? kc * 64 : (kc - 2) * 64;

    u64 acc[32];
#pragma unroll
    for (int m = 0; m < 32; m++) acc[m] = 0ull;

#pragma unroll
    for (int it = 0; it < 2; it++) {
        float4 wr[4];
#pragma unroll
        for (int r = 0; r < 4; r++)
            wr[r] = *((const float4*)(wbase + (size_t)(j0 + r) * rowlen + koff)
                      + it * 32 + lane);

        u64 w2[4][4];
#pragma unroll
        for (int r = 0; r < 4; r++) {
            w2[r][0] = pack2(wr[r].x, wr[r].x);
            w2[r][1] = pack2(wr[r].y, wr[r].y);
            w2[r][2] = pack2(wr[r].z, wr[r].z);
            w2[r][3] = pack2(wr[r].w, wr[r].w);
        }

        const int k4 = zoff + it * 32 + lane;
#pragma unroll
        for (int bp = 0; bp < 8; bp++) {
            float4 zl = __ldg(zsrc + (2 * bp)     * rowf4 + k4);
            float4 zh = __ldg(zsrc + (2 * bp + 1) * rowf4 + k4);
            u64 z0 = pack2(zl.x, zh.x);
            u64 z1 = pack2(zl.y, zh.y);
            u64 z2 = pack2(zl.z, zh.z);
            u64 z3 = pack2(zl.w, zh.w);
#pragma unroll
            for (int r = 0; r < 4; r++) {
                fma2(acc[r * 8 + bp], w2[r][0], z0);
                fma2(acc[r * 8 + bp], w2[r][1], z1);
                fma2(acc[r * 8 + bp], w2[r][2], z2);
                fma2(acc[r * 8 + bp], w2[r][3], z3);
            }
        }
    }

    float a[64];
#pragma unroll
    for (int r = 0; r < 4; r++)
#pragma unroll
        for (int bp = 0; bp < 8; bp++)
            unpack2(acc[r * 8 + bp], a[r * 16 + 2 * bp], a[r * 16 + 2 * bp + 1]);

    // Multi-value butterfly reduction: 64 values -> 2 per lane (62 shuffles).
#pragma unroll
    for (int k = 0; k < 5; k++) {
        const int d = 1 << k;
        const int n = 64 >> k;
        const bool hi = (lane >> k) & 1;
#pragma unroll
        for (int m = 0; m < 32; m++) {
            if (m < n / 2) {
                float mine = hi ? a[m] : a[m + n / 2];
                float got  = __shfl_xor_sync(0xffffffffu, mine, d);
                a[m] = (hi ? a[m + n / 2] : a[m]) + got;
            }
        }
    }

    const unsigned rev = __brev((unsigned)lane) >> 27;
#pragma unroll
    for (int j = 0; j < 2; j++) {
        const unsigned v = (rev << 1) | j;
        const int jj = v >> 4;
        const int b  = v & 15;
        g_part[kc][g * BH + b * HH + j0 + jj] = a[j];
    }
}

// ---------------------------------------------------------------------------
// Kernel 2: fused pointwise + trace, PDL secondary. Everything that does not
// depend on g_part (smem staging, bias/c_last/e_b loads) runs BEFORE
// cudaGridDependencySynchronize(); only g_part reads + activations after.
// ---------------------------------------------------------------------------
#define JT 16

__global__ __launch_bounds__(256) void trace_kernel(
    const float* __restrict__ x, const float* __restrict__ h_last,
    const float* __restrict__ c_last,
    const float* __restrict__ b_i, const float* __restrict__ b_f,
    const float* __restrict__ b_o, const float* __restrict__ b_c,
    const float* __restrict__ eb_i, const float* __restrict__ eb_f,
    const float* __restrict__ eb_c,
    const float* __restrict__ e_ix, const float* __restrict__ e_ih,
    const float* __restrict__ e_fx, const float* __restrict__ e_fh,
    const float* __restrict__ e_cx, const float* __restrict__ e_ch,
    float* __restrict__ out)
{
    __shared__ float4 sx[II / 4];   // 2KB
    __shared__ float4 sh[HH / 4];   // 4KB
    __shared__ float4 scf[JT];

    const int tid = threadIdx.x;
    const int b   = blockIdx.y;
    const int j0  = blockIdx.x * JT;

    // -------- gates-independent prologue (overlaps gates under PDL) --------
    if (tid < 128) sx[tid] = ((const float4*)(x + b * II))[tid];
    sh[tid] = ((const float4*)(h_last + b * HH))[tid];

    float bi = 0.f, bf = 0.f, bo = 0.f, bc = 0.f;
    float cl = 0.f, ebi = 0.f, ebf = 0.f, ebc = 0.f;
    int idx = 0;
    if (tid < JT) {
        const int j = j0 + tid;
        idx = b * HH + j;
        bi = b_i[j];  bf = b_f[j];  bo = b_o[j];  bc = b_c[j];
        cl = c_last[idx];
        ebi = eb_i[idx]; ebf = eb_f[idx]; ebc = eb_c[idx];
    }

    // -------- wait for gates' g_part to be visible --------
    cudaGridDependencySynchronize();

    if (tid < JT) {
        float pi = bi, pf = bf, po = bo, pc = bc;
#pragma unroll
        for (int c = 0; c < NKC; c++) {
            pi += g_part[c][0 * BH + idx];
            pf += g_part[c][1 * BH + idx];
            po += g_part[c][2 * BH + idx];
            pc += g_part[c][3 * BH + idx];
        }

        float i  = 1.f / (1.f + expf(-pi));
        float f  = 1.f / (1.f + expf(-pf));
        float o  = 1.f / (1.f + expf(-po));
        float ch = tanhf(pc);

        float c = fmaf(f, cl, i * ch);
        float h = o * c;
        float di  = i * (1.f - i);
        float df  = f * (1.f - f);
        float dch = 1.f - ch * ch;
        float ai = di * ch;
        float af = df * cl;
        float ac = dch * i;

        out[OFF_H + idx]   = h;
        out[OFF_C + idx]   = c;
        out[OFF_EBI + idx] = fmaf(ebi, f, ai);
        out[OFF_EBF + idx] = fmaf(ebf, f, af);
        out[OFF_EBC + idx] = fmaf(ebc, f, ac);
        scf[tid] = make_float4(f, ai, af, ac);
    }
    __syncthreads();

    const size_t baseH = (size_t)(b * HH + j0) * (HH / 4);
    const size_t baseI = (size_t)(b * HH + j0) * (II / 4);

    const float4 hv = sh[tid];
    const float4 xv = sx[tid & 127];
    const int xsel = tid >> 7;

#define TRACE_H(SRC, OFF, SEL)                                              \
    {                                                                       \
        const float4* ein = (const float4*)(SRC) + baseH;                   \
        float4* eo = (float4*)(out + (OFF)) + baseH;                        \
        _Pragma("unroll")                                                   \
        for (int it = 0; it < JT; it++) {                                   \
            const int t = tid + it * 256;                                   \
            float4 cf = scf[it];                                            \
            float fv = cf.x, aa = cf.SEL;                                   \
            float4 e  = __ldcs(ein + t);                                    \
            float4 rr;                                                      \
            rr.x = fmaf(e.x, fv, aa * hv.x);                                \
            rr.y = fmaf(e.y, fv, aa * hv.y);                                \
            rr.z = fmaf(e.z, fv, aa * hv.z);                                \
            rr.w = fmaf(e.w, fv, aa * hv.w);                                \
            __stcs(eo + t, rr);                                             \
        }                                                                   \
    }

#define TRACE_X(SRC, OFF, SEL)                                              \
    {                                                                       \
        const float4* ein = (const float4*)(SRC) + baseI;                   \
        float4* eo = (float4*)(out + (OFF)) + baseI;                        \
        _Pragma("unroll")                                                   \
        for (int it = 0; it < JT / 2; it++) {                               \
            const int t = tid + it * 256;                                   \
            float4 cf = scf[it * 2 + xsel];                                 \
            float fv = cf.x, aa = cf.SEL;                                   \
            float4 e  = __ldcs(ein + t);                                    \
            float4 rr;                                                      \
            rr.x = fmaf(e.x, fv, aa * xv.x);                                \
            rr.y = fmaf(e.y, fv, aa * xv.y);                                \
            rr.z = fmaf(e.z, fv, aa * xv.z);                                \
            rr.w = fmaf(e.w, fv, aa * xv.w);                                \
            __stcs(eo + t, rr);                                             \
        }                                                                   \
    }

    TRACE_H(e_ih, OFF_EWIH, y)
    TRACE_H(e_fh, OFF_EWFH, z)
    TRACE_H(e_ch, OFF_EWCH, w)
    TRACE_X(e_ix, OFF_EWIX, y)
    TRACE_X(e_fx, OFF_EWFX, z)
    TRACE_X(e_cx, OFF_EWCX, w)
}

// ---------------------------------------------------------------------------
extern "C" void kernel_launch(void* const* d_in, const int* in_sizes, int n_in,
                              void* d_out, int out_size)
{
    const float* x      = (const float*)d_in[0];
    const float* w_ix   = (const float*)d_in[1];
    const float* w_ih   = (const float*)d_in[2];
    const float* b_i    = (const float*)d_in[3];
    const float* w_fx   = (const float*)d_in[4];
    const float* w_fh   = (const float*)d_in[5];
    const float* b_f    = (const float*)d_in[6];
    const float* w_ox   = (const float*)d_in[7];
    const float* w_oh   = (const float*)d_in[8];
    const float* b_o    = (const float*)d_in[9];
    const float* w_cx   = (const float*)d_in[10];
    const float* w_ch   = (const float*)d_in[11];
    const float* b_c    = (const float*)d_in[12];
    const float* h_last = (const float*)d_in[13];
    const float* c_last = (const float*)d_in[14];
    const float* e_w_ix = (const float*)d_in[15];
    const float* e_w_ih = (const float*)d_in[16];
    const float* e_b_i  = (const float*)d_in[17];
    const float* e_w_fx = (const float*)d_in[18];
    const float* e_w_fh = (const float*)d_in[19];
    const float* e_b_f  = (const float*)d_in[20];
    const float* e_w_cx = (const float*)d_in[21];
    const float* e_w_ch = (const float*)d_in[22];
    const float* e_b_c  = (const float*)d_in[23];
    float* out = (float*)d_out;

    GatePtrs p;
    p.wx[0] = w_ix; p.wx[1] = w_fx; p.wx[2] = w_ox; p.wx[3] = w_cx;
    p.wh[0] = w_ih; p.wh[1] = w_fh; p.wh[2] = w_oh; p.wh[3] = w_ch;

    dim3 g1(HH / 16, 4, NKC);
    gates_kernel<<<g1, 128>>>(x, h_last, p);

    dim3 g3(HH / JT, Bb);
    cudaLaunchConfig_t cfg = {};
    cfg.gridDim = g3;
    cfg.blockDim = dim3(256, 1, 1);
    cfg.dynamicSmemBytes = 0;
    cfg.stream = 0;
    cudaLaunchAttribute attrs[1];
    attrs[0].id = cudaLaunchAttributeProgrammaticStreamSerialization;
    attrs[0].val.programmaticStreamSerializationAllowed = 1;
    cfg.attrs = attrs;
    cfg.numAttrs = 1;

    cudaLaunchKernelEx(&cfg, trace_kernel,
                       x, h_last, c_last, b_i, b_f, b_o, b_c,
                       e_b_i, e_b_f, e_b_c,
                       e_w_ix, e_w_ih, e_w_fx, e_w_fh,
                       e_w_cx, e_w_ch, out);
}